// round 10
// baseline (speedup 1.0000x reference)
#include <cuda_runtime.h>
#include <cstdint>

#define V_NUM 80000
#define P_NUM 20
#define C_OUT 64
#define NY 640
#define NX 640
#define B_NUM 4

static constexpr float BN_EPS = 0.001f;
static constexpr size_t PLANE  = (size_t)NY * NX;                 // 409600
static constexpr size_t CANVAS = (size_t)B_NUM * C_OUT * PLANE;   // 104857600
static constexpr int    MAP_N  = B_NUM * NY * NX;                 // 1638400

__device__ __constant__ float kVX   = 100.0f / 640.0f;
__device__ __constant__ float kXOFF = 100.0f / 640.0f * 0.5f - 50.0f;

// Scratch. g_map / g_pix are zero-initialized at module load; the
// self-validation scheme (g_pix[g_map[pix]] == pix) makes per-call clearing
// unnecessary.
__device__ float g_feats[(size_t)V_NUM * C_OUT];   // 20.5 MB
__device__ int   g_map[MAP_N];                     // pixel -> voxel id
__device__ int   g_pix[V_NUM];                     // voxel id -> pixel

// ---- packed f32x2 helpers --------------------------------------------------
__device__ __forceinline__ unsigned long long pk2(float lo, float hi) {
    unsigned long long r;
    asm("mov.b64 %0, {%1, %2};" : "=l"(r) : "f"(lo), "f"(hi));
    return r;
}
__device__ __forceinline__ unsigned long long dup2(float v) {
    unsigned long long r;
    asm("mov.b64 %0, {%1, %1};" : "=l"(r) : "f"(v));
    return r;
}
__device__ __forceinline__ unsigned long long fma2(unsigned long long a,
                                                   unsigned long long b,
                                                   unsigned long long c) {
    unsigned long long d;
    asm("fma.rn.f32x2 %0, %1, %2, %3;" : "=l"(d) : "l"(a), "l"(b), "l"(c));
    return d;
}
__device__ __forceinline__ unsigned long long mul2(unsigned long long a,
                                                   unsigned long long b) {
    unsigned long long d;
    asm("mul.rn.f32x2 %0, %1, %2;" : "=l"(d) : "l"(a), "l"(b), "l"(b));
    return d;
}
__device__ __forceinline__ void unpk2(unsigned long long v, float& lo, float& hi) {
    asm("mov.b64 {%0, %1}, %2;" : "=f"(lo), "=f"(hi) : "l"(v));
}

// ---------------------------------------------------------------------------
// Kernel 1: per-voxel features. One warp per voxel; lane owns channels
// {lane, lane+32} packed as f32x2. No smem, no barrier, no shuffle tree:
//  - voxel tile prefetched (DRAM) while the per-warp fold (ALU) executes
//  - point sums for the mean accumulate inside the dot loop (redundantly in
//    all lanes) instead of a serial 5-stage shuffle reduction
//  - max_p(dot_p + E) = max_p(dot_p) + E  ->  E applied once at the end
// ---------------------------------------------------------------------------
__global__ void __launch_bounds__(128)
compute_feats_kernel(const float* __restrict__ voxels,
                     const int*   __restrict__ num_points,
                     const int4*  __restrict__ coors4,
                     const float* __restrict__ W,
                     const float* __restrict__ gamma,
                     const float* __restrict__ beta,
                     const float* __restrict__ rmean,
                     const float* __restrict__ rvar)
{
    const int v = blockIdx.x * (blockDim.x >> 5) + (threadIdx.x >> 5);
    if (v >= V_NUM) return;
    const int lane = threadIdx.x & 31;

    // ---- issue the DRAM traffic first (tile prefetch + scalars) ----
    const float4* __restrict__ vox =
        reinterpret_cast<const float4*>(voxels) + (size_t)v * P_NUM;
    const int  npv_raw = num_points[v];
    const int4 cr      = coors4[v];
    float4 pre;                       // prefetch: pulls the 320B tile into L1
    if (lane < P_NUM) pre = vox[lane];

    // ---- per-warp fold (ALU work, overlaps the prefetch latency) ----
    const int c0 = lane, c1 = lane + 32;
    const float s0 = rsqrtf(rvar[c0] + BN_EPS) * gamma[c0];
    const float s1 = rsqrtf(rvar[c1] + BN_EPS) * gamma[c1];
    const float bb0 = beta[c0] - rmean[c0] * s0;
    const float bb1 = beta[c1] - rmean[c1] * s1;

    float sw0[9], sw1[9];
    #pragma unroll
    for (int i = 0; i < 9; i++) {
        sw0[i] = W[i * C_OUT + c0] * s0;     // L1/L2 hits after first warps
        sw1[i] = W[i * C_OUT + c1] * s1;
    }
    const unsigned long long A2 = pk2(sw0[0] + sw0[4] + sw0[7],
                                      sw1[0] + sw1[4] + sw1[7]);
    const unsigned long long B2 = pk2(sw0[1] + sw0[5] + sw0[8],
                                      sw1[1] + sw1[5] + sw1[8]);
    const unsigned long long C2 = pk2(sw0[2] + sw0[6], sw1[2] + sw1[6]);
    const unsigned long long D2 = pk2(sw0[3], sw1[3]);

    int npv = npv_raw;
    npv = npv < 0 ? 0 : (npv > P_NUM ? P_NUM : npv);

    // ---- fused loop: dot-max + coordinate sums (mean) ----
    float ma0 = -3.4e38f, mb0 = -3.4e38f;
    float ma1 = -3.4e38f, mb1 = -3.4e38f;
    float sx = 0.f, sy = 0.f, sz = 0.f;
    int p = 0;
    for (; p + 1 < npv; p += 2) {
        const float4 q0 = vox[p];            // L1 hits (prefetched)
        const float4 q1 = vox[p + 1];
        unsigned long long d0 = fma2(dup2(q0.w), D2, mul2(dup2(q0.z), C2));
        unsigned long long d1 = fma2(dup2(q1.w), D2, mul2(dup2(q1.z), C2));
        d0 = fma2(dup2(q0.y), B2, d0);   d1 = fma2(dup2(q1.y), B2, d1);
        d0 = fma2(dup2(q0.x), A2, d0);   d1 = fma2(dup2(q1.x), A2, d1);
        sx += q0.x + q1.x;
        sy += q0.y + q1.y;
        sz += q0.z + q1.z;
        float l0, h0, l1, h1;
        unpk2(d0, l0, h0);  unpk2(d1, l1, h1);
        ma0 = fmaxf(ma0, l0);  mb0 = fmaxf(mb0, l1);
        ma1 = fmaxf(ma1, h0);  mb1 = fmaxf(mb1, h1);
    }
    if (p < npv) {
        const float4 q0 = vox[p];
        unsigned long long d0 = fma2(dup2(q0.w), D2, mul2(dup2(q0.z), C2));
        d0 = fma2(dup2(q0.y), B2, d0);
        d0 = fma2(dup2(q0.x), A2, d0);
        sx += q0.x;  sy += q0.y;  sz += q0.z;
        float l0, h0;
        unpk2(d0, l0, h0);
        ma0 = fmaxf(ma0, l0);
        ma1 = fmaxf(ma1, h0);
    }
    const float md0 = fmaxf(ma0, mb0);
    const float md1 = fmaxf(ma1, mb1);

    // ---- mean + E (short tail chain) ----
    const float inv_n = 1.0f / (float)(npv > 1 ? npv : 1);
    const float mx = sx * inv_n, my = sy * inv_n, mz = sz * inv_n;
    const float cx = (float)cr.w * kVX + kXOFF;
    const float cy = (float)cr.z * kVX + kXOFF;

    const float E0 = bb0 - (mx * sw0[4] + my * sw0[5] + mz * sw0[6]
                          + cx * sw0[7] + cy * sw0[8]);
    const float E1 = bb1 - (mx * sw1[4] + my * sw1[5] + mz * sw1[6]
                          + cx * sw1[7] + cy * sw1[8]);

    float m0 = md0 + E0;
    float m1 = md1 + E1;
    if (npv < P_NUM) { m0 = fmaxf(m0, bb0); m1 = fmaxf(m1, bb1); }

    g_feats[(size_t)v * C_OUT + c0] = fmaxf(m0, 0.0f);
    g_feats[(size_t)v * C_OUT + c1] = fmaxf(m1, 0.0f);
    if (lane == 0) {
        const int pix = cr.x * (NY * NX) + cr.z * NX + cr.w;
        g_map[pix] = v;
        g_pix[v]   = pix;
    }
}

// ---------------------------------------------------------------------------
// Kernel 2: coalesced render of canvas + occ (proven shape, ~62% DRAM ceiling).
// Block = 256 threads, owns 128 pixels of one (b,y) row, all 64 channels.
// ---------------------------------------------------------------------------
__global__ void __launch_bounds__(256)
render_kernel(float* __restrict__ out)
{
    __shared__ int map_s[128];

    const int b  = blockIdx.z;
    const int y  = blockIdx.y;
    const int x0 = blockIdx.x * 128;
    const int t  = threadIdx.x;

    const int pix_base = b * (NY * NX) + y * NX + x0;
    if (t < 128) {
        const int pix = pix_base + t;
        int v = g_map[pix];
        if (g_pix[v] != pix) v = -1;   // stale / zero-init -> invalid
        map_s[t] = v;
    }
    __syncthreads();

    const int xq  = (t & 31) * 4;
    const int row = t >> 5;            // 0..7

    const int v0 = map_s[xq + 0];
    const int v1 = map_s[xq + 1];
    const int v2 = map_s[xq + 2];
    const int v3 = map_s[xq + 3];

    const size_t out_xbase = (size_t)y * NX + x0 + xq;

    #pragma unroll
    for (int k = 0; k < 8; k++) {
        const int c = row + k * 8;
        float4 val = make_float4(0.f, 0.f, 0.f, 0.f);
        if (v0 >= 0) val.x = g_feats[(size_t)v0 * C_OUT + c];
        if (v1 >= 0) val.y = g_feats[(size_t)v1 * C_OUT + c];
        if (v2 >= 0) val.z = g_feats[(size_t)v2 * C_OUT + c];
        if (v3 >= 0) val.w = g_feats[(size_t)v3 * C_OUT + c];
        float4* dst = reinterpret_cast<float4*>(
            out + ((size_t)(b * C_OUT + c)) * PLANE + out_xbase);
        __stcs(dst, val);              // streaming: keep feats/map in L2
    }

    if (t < 32) {
        float4 occ = make_float4(v0 >= 0 ? 1.f : 0.f,
                                 v1 >= 0 ? 1.f : 0.f,
                                 v2 >= 0 ? 1.f : 0.f,
                                 v3 >= 0 ? 1.f : 0.f);
        float4* dst = reinterpret_cast<float4*>(
            out + CANVAS + (size_t)b * PLANE + out_xbase);
        __stcs(dst, occ);
    }
}

extern "C" void kernel_launch(void* const* d_in, const int* in_sizes, int n_in,
                              void* d_out, int out_size)
{
    const float* voxels     = (const float*)d_in[0];
    const int*   num_points = (const int*)  d_in[1];
    const int4*  coors4     = (const int4*) d_in[2];
    const float* W          = (const float*)d_in[3];
    const float* gamma      = (const float*)d_in[4];
    const float* beta       = (const float*)d_in[5];
    const float* rmean      = (const float*)d_in[6];
    const float* rvar       = (const float*)d_in[7];
    float* out = (float*)d_out;

    compute_feats_kernel<<<(V_NUM + 3) / 4, 128>>>(voxels, num_points, coors4,
                                                   W, gamma, beta, rmean, rvar);

    dim3 grid(NX / 128, NY, B_NUM);
    render_kernel<<<grid, 256>>>(out);
}